// round 4
// baseline (speedup 1.0000x reference)
#include <cuda_runtime.h>

#define NL 128   // rows of lines tables
#define CL 32    // embedding width
#define HD 128   // hidden dim
#define NFLAG (3 * NL)
#define SFBYTES (NFLAG * 32 * 4)   // 48 KB: [axis*128+k][lane]

// Persistent device scratch (allocations are forbidden). Left zeroed /
// fully-rewritten at the end of every launch => deterministic graph replays.
__device__ unsigned g_flags[NFLAG];   // occupancy flags per (axis, row)
__device__ float    g_pre[8 * NL];    // [combo*128 + r] precomputed head outputs
__device__ unsigned g_done;           // block completion counter

__global__ __launch_bounds__(256, 4) void k_fused(
    const float4* __restrict__ c4, int n128,
    const float*  __restrict__ cflat, int nfloats,
    const float*  __restrict__ lines0, const float* __restrict__ lines1,
    const float*  __restrict__ lines2, const float* __restrict__ w1,
    const float*  __restrict__ b1, const float* __restrict__ w2,
    const float*  __restrict__ b2, float* __restrict__ out, int nout)
{
    extern __shared__ unsigned sflag[];   // [ (axis*NL + k) * 32 + lane ]
    __shared__ float s_red[8];
    __shared__ float s_feats[CL];
    __shared__ float s_c0;
    __shared__ int   s_last;

    const int tid  = threadIdx.x;
    const int lane = tid & 31;
    const int wid  = tid >> 5;

    // Zero the per-lane flag columns (vectorized: 12 uint4 per thread).
    {
        uint4 z = make_uint4(0u, 0u, 0u, 0u);
        uint4* p4 = (uint4*)sflag;
        #pragma unroll
        for (int i = tid; i < NFLAG * 32 / 4; i += 256) p4[i] = z;
    }

    // ------------------------------------------------------------------
    // Phase A (all blocks): c0 = sum_j w2_j * relu(b1_j) + b2
    // ------------------------------------------------------------------
    {
        float v = 0.f;
        if (tid < HD) v = fmaxf(__ldg(&b1[tid]), 0.f) * __ldg(&w2[tid]);
        #pragma unroll
        for (int o = 16; o; o >>= 1) v += __shfl_down_sync(~0u, v, o);
        if (tid < HD && lane == 0) s_red[wid] = v;
        __syncthreads();
        if (tid == 0) s_c0 = s_red[0] + s_red[1] + s_red[2] + s_red[3] + __ldg(&b2[0]);
        __syncthreads();
    }

    // ------------------------------------------------------------------
    // Phase B: precompute g_pre[combo][r] for 8 combos x 128 rows,
    // grid-strided (trip count uniform within a block -> syncthreads safe).
    // ------------------------------------------------------------------
    for (unsigned e = blockIdx.x; e < 8 * NL; e += gridDim.x) {
        const int combo = e >> 7;
        const int r     = e & (NL - 1);
        if (tid < CL) {
            float x = __ldg(&lines0[r * CL + tid]) * (float)(combo & 1);
            float y = __ldg(&lines1[r * CL + tid]) * (float)((combo >> 1) & 1);
            float z = __ldg(&lines2[r * CL + tid]) * (float)((combo >> 2) & 1);
            float f1 = x + y + z;
            float f2 = (x * y + x * z + y * z) / 0.4f;
            float f3 = x * y * z / 0.16000000000000003f;
            s_feats[tid] = f1 + f2 + f3;
        }
        __syncthreads();
        float term = 0.f;
        if (tid < HD) {
            float acc = __ldg(&b1[tid]);
            const float4* w4 = (const float4*)(w1 + tid * CL);
            #pragma unroll
            for (int q = 0; q < CL / 4; q++) {
                float4 wv = __ldg(&w4[q]);
                acc = fmaf(wv.x, s_feats[q * 4 + 0], acc);
                acc = fmaf(wv.y, s_feats[q * 4 + 1], acc);
                acc = fmaf(wv.z, s_feats[q * 4 + 2], acc);
                acc = fmaf(wv.w, s_feats[q * 4 + 3], acc);
            }
            term = fmaxf(acc, 0.f) * __ldg(&w2[tid]);
        }
        #pragma unroll
        for (int o = 16; o; o >>= 1) term += __shfl_down_sync(~0u, term, o);
        __syncthreads();
        if (tid < HD && lane == 0) s_red[wid] = term;
        __syncthreads();
        if (tid == 0)
            g_pre[e] = s_red[0] + s_red[1] + s_red[2] + s_red[3] + __ldg(&b2[0]);
        __syncthreads();
    }
    __syncthreads();   // sflag zeroing complete before scan stores

    // ------------------------------------------------------------------
    // Phase C: scan coordinates -> per-lane flag columns (bank-conflict-free
    // predicated STS). Warp consumes 96 consecutive float4s; flat idx
    // f = 4*(w*96+lane+32s)+i, axis(f) = (lane+2s+i)%3 = (p+j)%3 with
    // p = lane%3 and compile-time j. k = round((v+2)*32) ==
    // __float2int_rn(fmaf(v,32,64)) bit-exactly. Unroll x2 for MLP.
    // ------------------------------------------------------------------
    const int p = lane % 3;
    int d1 = p + 1; if (d1 == 3) d1 = 0;
    int d2 = d1 + 1; if (d2 == 3) d2 = 0;
    // Column base for axis a at this lane: a*NL*32 + lane; store at +k*32.
    const unsigned B0 = ((unsigned)p  << 12) + lane;
    const unsigned B1 = ((unsigned)d1 << 12) + lane;
    const unsigned B2 = ((unsigned)d2 << 12) + lane;

#define PROC(v, BB) {                                                   \
        float t_ = fmaf((v), 32.0f, 64.0f);                             \
        int k_ = __float2int_rn(t_);                                    \
        if ((unsigned)k_ < (unsigned)NL)                                \
            sflag[(BB) + ((unsigned)k_ << 5)] = 1u; }

#define PROC_CHUNK(f0, f1, f2)                                          \
        PROC(f0.x, B0) PROC(f0.y, B1) PROC(f0.z, B2) PROC(f0.w, B0)     \
        PROC(f1.x, B2) PROC(f1.y, B0) PROC(f1.z, B1) PROC(f1.w, B2)     \
        PROC(f2.x, B1) PROC(f2.y, B2) PROC(f2.z, B0) PROC(f2.w, B1)

    const int nwarps  = gridDim.x * 8;
    const int wg      = blockIdx.x * 8 + wid;
    const int nchunks = n128 / 96;

    int w = wg;
    for (; w + nwarps < nchunks; w += 2 * nwarps) {
        const int ba = w * 96 + lane;
        const int bb = (w + nwarps) * 96 + lane;
        float4 a0 = c4[ba];
        float4 a1 = c4[ba + 32];
        float4 a2 = c4[ba + 64];
        float4 e0 = c4[bb];
        float4 e1 = c4[bb + 32];
        float4 e2 = c4[bb + 64];
        PROC_CHUNK(a0, a1, a2)
        PROC_CHUNK(e0, e1, e2)
    }
    if (w < nchunks) {
        const int ba = w * 96 + lane;
        float4 a0 = c4[ba];
        float4 a1 = c4[ba + 32];
        float4 a2 = c4[ba + 64];
        PROC_CHUNK(a0, a1, a2)
    }

    const int gid = blockIdx.x * 256 + tid;
    const int gsz = gridDim.x * 256;

    // float4 tail (n128 % 96) — runtime axis computation (empty for 12.58M).
    for (int q = nchunks * 96 + gid; q < n128; q += gsz) {
        float4 f = c4[q];
        float vv[4] = {f.x, f.y, f.z, f.w};
        #pragma unroll
        for (int i = 0; i < 4; i++) {
            int d = (int)(((q << 2) + i) % 3);
            int k_ = __float2int_rn(fmaf(vv[i], 32.0f, 64.0f));
            if ((unsigned)k_ < (unsigned)NL)
                sflag[(((unsigned)d << 12) + lane) + ((unsigned)k_ << 5)] = 1u;
        }
    }
    // scalar tail (nfloats % 4) — safety only.
    for (int q = (n128 << 2) + gid; q < nfloats; q += gsz) {
        int d = (int)(q % 3);
        int k_ = __float2int_rn(fmaf(cflat[q], 32.0f, 64.0f));
        if ((unsigned)k_ < (unsigned)NL)
            sflag[(((unsigned)d << 12) + lane) + ((unsigned)k_ << 5)] = 1u;
    }
#undef PROC_CHUNK
#undef PROC

    __syncthreads();
    // Merge: warp `wid` handles rows wid, wid+8, ... Lane l reads column l
    // (bank l: conflict-free), warp-OR, lane 0 publishes.
    for (int r = wid; r < NFLAG; r += 8) {
        unsigned v = sflag[(r << 5) + lane];
        v = __reduce_or_sync(~0u, v);
        if (v && lane == 0) g_flags[r] = 1u;  // benign race: all write 1
    }

    // ------------------------------------------------------------------
    // Phase E: fill out[NL .. nout) with c0 (vectorized, all blocks).
    // ------------------------------------------------------------------
    {
        const float c0 = s_c0;
        const float4 cv = make_float4(c0, c0, c0, c0);
        float4* out4 = (float4*)out;
        const int n4 = nout >> 2;
        for (int q = (NL / 4) + gid; q < n4; q += gsz) out4[q] = cv;
        for (int q = (n4 << 2) + gid; q < nout; q += gsz)
            if (q >= NL) out[q] = c0;
    }

    // ------------------------------------------------------------------
    // Phase F: last block finalizes rows [0, NL) and resets scratch.
    // ------------------------------------------------------------------
    __threadfence();
    if (tid == 0) {
        unsigned t = atomicAdd(&g_done, 1u);
        s_last = (t == (unsigned)(gridDim.x - 1)) ? 1 : 0;
    }
    __syncthreads();
    if (s_last) {
        __threadfence();  // acquire: see all blocks' g_flags / g_pre writes
        if (tid < NL) {
            const int r = tid;
            unsigned fx = __ldcg(&g_flags[r])          ? 1u : 0u;
            unsigned fy = __ldcg(&g_flags[NL + r])     ? 1u : 0u;
            unsigned fz = __ldcg(&g_flags[2 * NL + r]) ? 1u : 0u;
            unsigned combo = fx | (fy << 1) | (fz << 2);
            if (r < nout) out[r] = __ldcg(&g_pre[combo * NL + r]);
        }
        __syncthreads();
        for (int i = tid; i < NFLAG; i += 256) g_flags[i] = 0u;  // reset
        if (tid == 0) g_done = 0u;
    }
}

// ---------------------------------------------------------------------------
extern "C" void kernel_launch(void* const* d_in, const int* in_sizes, int n_in,
                              void* d_out, int out_size) {
    const float* coords = (const float*)d_in[0];
    const float* lines0 = (const float*)d_in[1];
    const float* lines1 = (const float*)d_in[2];
    const float* lines2 = (const float*)d_in[3];
    const float* w1     = (const float*)d_in[4];
    const float* b1     = (const float*)d_in[5];
    const float* w2     = (const float*)d_in[6];
    const float* b2     = (const float*)d_in[7];
    float* out = (float*)d_out;

    static bool attr_set = false;
    if (!attr_set) {
        cudaFuncSetAttribute(k_fused,
                             cudaFuncAttributeMaxDynamicSharedMemorySize,
                             SFBYTES);
        attr_set = true;
    }

    const int nfloats = in_sizes[0];
    const int n128 = nfloats >> 2;

    k_fused<<<592, 256, SFBYTES>>>((const float4*)coords, n128, coords, nfloats,
                                   lines0, lines1, lines2, w1, b1, w2, b2,
                                   out, out_size);
}

// round 5
// speedup vs baseline: 2.1023x; 2.1023x over previous
#include <cuda_runtime.h>

#define NL 128   // rows of lines tables
#define CL 32    // embedding width
#define HD 128   // hidden dim
#define NFLAG (3 * NL)
#define P1CH 1024          // phase-1 sample: first 1024 chunks (1.5 MB)
#define GRID 592           // 4 blocks/SM x 148 SMs: single co-resident wave
#define TPB  256

// Persistent device scratch (allocations forbidden). Reset at the end of
// every launch by the last block => deterministic graph replays.
__device__ unsigned g_maskbits[12];   // packed flags: [axis*4 + word32]
__device__ float    g_pre[8 * NL];    // [combo*128 + r] precomputed head outputs
__device__ unsigned g_p1done;         // phase-1 arrival counter (grid barrier)
__device__ unsigned g_done;           // final completion counter

__global__ __launch_bounds__(TPB, 4) void k_fused(
    const float4* __restrict__ c4, int n128,
    const float*  __restrict__ cflat, int nfloats,
    const float*  __restrict__ lines0, const float* __restrict__ lines1,
    const float*  __restrict__ lines2, const float* __restrict__ w1,
    const float*  __restrict__ b1, const float* __restrict__ w2,
    const float*  __restrict__ b2, float* __restrict__ out, int nout)
{
    __shared__ unsigned sflag[NFLAG];
    __shared__ float    s_red[8];
    __shared__ float    s_feats[CL];
    __shared__ float    s_c0;
    __shared__ int      s_complete;
    __shared__ int      s_last;

    const int tid  = threadIdx.x;
    const int lane = tid & 31;
    const int wid  = tid >> 5;

    for (int i = tid; i < NFLAG; i += TPB) sflag[i] = 0u;

    // ------------------------------------------------------------------
    // Phase A: c0 = sum_j w2_j * relu(b1_j) + b2
    // ------------------------------------------------------------------
    {
        float v = 0.f;
        if (tid < HD) v = fmaxf(__ldg(&b1[tid]), 0.f) * __ldg(&w2[tid]);
        #pragma unroll
        for (int o = 16; o; o >>= 1) v += __shfl_down_sync(~0u, v, o);
        if (tid < HD && lane == 0) s_red[wid] = v;
        __syncthreads();
        if (tid == 0) s_c0 = s_red[0] + s_red[1] + s_red[2] + s_red[3] + __ldg(&b2[0]);
        __syncthreads();
    }

    // ------------------------------------------------------------------
    // Phase C1: sample scan. Warp wg scans chunk wg for wg < Pc.
    // Chunk layout: warp reads 96 consecutive float4s; flat idx
    // f = 4*(w*96+lane+32s)+i, axis(f) = (lane+2s+i)%3 = (p+j)%3 with
    // p = lane%3 and compile-time j. k = round((v+2)*32) ==
    // __float2int_rn(fmaf(v,32,64)) bit-exactly (pow-2 scale commutes
    // with rounding; round-half-even both).
    // ------------------------------------------------------------------
    const int p = lane % 3;
    int e1 = p + 1; if (e1 == 3) e1 = 0;
    int e2 = e1 + 1; if (e2 == 3) e2 = 0;
    const unsigned B0 = (unsigned)p  * NL;
    const unsigned B1 = (unsigned)e1 * NL;
    const unsigned B2 = (unsigned)e2 * NL;

#define PROC(v, BB) {                                                \
        float t_ = fmaf((v), 32.0f, 64.0f);                          \
        int k_ = __float2int_rn(t_);                                 \
        if ((unsigned)k_ < (unsigned)NL) sflag[(BB) + k_] = 1u; }

#define PROC_CHUNK(f0, f1, f2)                                       \
        PROC(f0.x, B0) PROC(f0.y, B1) PROC(f0.z, B2) PROC(f0.w, B0)  \
        PROC(f1.x, B2) PROC(f1.y, B0) PROC(f1.z, B1) PROC(f1.w, B2)  \
        PROC(f2.x, B1) PROC(f2.y, B2) PROC(f2.z, B0) PROC(f2.w, B1)

    const int nwarps  = gridDim.x * (TPB / 32);
    const int wg      = blockIdx.x * (TPB / 32) + wid;
    const int nchunks = n128 / 96;
    const int Pc      = (nchunks < P1CH) ? nchunks : P1CH;

    if (wg < Pc) {
        const int ba = wg * 96 + lane;
        float4 a0 = c4[ba];
        float4 a1 = c4[ba + 32];
        float4 a2 = c4[ba + 64];
        PROC_CHUNK(a0, a1, a2)
    }
    __syncthreads();

    // Merge sample flags: ballot-pack 12 words, atomicOr to global.
    {
        unsigned bal = __ballot_sync(~0u, sflag[wid * 32 + lane] != 0u);
        if (lane == 0 && bal) atomicOr(&g_maskbits[wid], bal);
        if (wid < 4) {
            int j = wid + 8;
            unsigned b2_ = __ballot_sync(~0u, sflag[j * 32 + lane] != 0u);
            if (lane == 0 && b2_) atomicOr(&g_maskbits[j], b2_);
        }
    }
    __threadfence();
    __syncthreads();
    if (tid == 0) atomicAdd(&g_p1done, 1u);

    // ------------------------------------------------------------------
    // Phase B (overlaps the grid barrier): g_pre[combo][r], grid-strided.
    // ------------------------------------------------------------------
    for (unsigned e = blockIdx.x; e < 8 * NL; e += gridDim.x) {
        const int combo = e >> 7;
        const int r     = e & (NL - 1);
        if (tid < CL) {
            float x = __ldg(&lines0[r * CL + tid]) * (float)(combo & 1);
            float y = __ldg(&lines1[r * CL + tid]) * (float)((combo >> 1) & 1);
            float z = __ldg(&lines2[r * CL + tid]) * (float)((combo >> 2) & 1);
            float f1 = x + y + z;
            float f2 = (x * y + x * z + y * z) / 0.4f;
            float f3 = x * y * z / 0.16000000000000003f;
            s_feats[tid] = f1 + f2 + f3;
        }
        __syncthreads();
        float term = 0.f;
        if (tid < HD) {
            float acc = __ldg(&b1[tid]);
            const float4* w4 = (const float4*)(w1 + tid * CL);
            #pragma unroll
            for (int q = 0; q < CL / 4; q++) {
                float4 wv = __ldg(&w4[q]);
                acc = fmaf(wv.x, s_feats[q * 4 + 0], acc);
                acc = fmaf(wv.y, s_feats[q * 4 + 1], acc);
                acc = fmaf(wv.z, s_feats[q * 4 + 2], acc);
                acc = fmaf(wv.w, s_feats[q * 4 + 3], acc);
            }
            term = fmaxf(acc, 0.f) * __ldg(&w2[tid]);
        }
        #pragma unroll
        for (int o = 16; o; o >>= 1) term += __shfl_down_sync(~0u, term, o);
        __syncthreads();
        if (tid < HD && lane == 0) s_red[wid] = term;
        __syncthreads();
        if (tid == 0)
            g_pre[e] = s_red[0] + s_red[1] + s_red[2] + s_red[3] + __ldg(&b2[0]);
        __syncthreads();
    }

    // ------------------------------------------------------------------
    // Grid barrier + completeness decision (uniform across all blocks).
    // Safe: grid == one co-resident wave (592 = 4/SM x 148, enforced by
    // __launch_bounds__(256,4) and smem < 57KB).
    // ------------------------------------------------------------------
    if (tid == 0) {
        const unsigned target = gridDim.x;
        unsigned c;
        do {
            asm volatile("ld.global.cg.u32 %0, [%1];" : "=r"(c) : "l"(&g_p1done));
            if (c >= target) break;
            __nanosleep(64);
        } while (true);
        __threadfence();
        int comp = 1;
        #pragma unroll
        for (int i = 0; i < 12; i++)
            comp &= (__ldcg(&g_maskbits[i]) == 0xFFFFFFFFu);
        s_complete = comp;
    }
    __syncthreads();

    const int gid = blockIdx.x * TPB + tid;
    const int gsz = gridDim.x * TPB;

    // ------------------------------------------------------------------
    // Fallback: flags not yet saturated -> scan everything not sampled.
    // (Flags are monotone, so when s_complete the rest of the input
    //  provably cannot change the output and is skipped.)
    // ------------------------------------------------------------------
    if (!s_complete) {
        int w = (wg < Pc) ? wg + nwarps : wg;
        for (; w < nchunks; w += nwarps) {
            const int ba = w * 96 + lane;
            float4 a0 = c4[ba];
            float4 a1 = c4[ba + 32];
            float4 a2 = c4[ba + 64];
            PROC_CHUNK(a0, a1, a2)
        }
        // float4 tail (n128 % 96)
        for (int q = nchunks * 96 + gid; q < n128; q += gsz) {
            float4 f = c4[q];
            float vv[4] = {f.x, f.y, f.z, f.w};
            #pragma unroll
            for (int i = 0; i < 4; i++) {
                int d = (int)(((q << 2) + i) % 3);
                int k_ = __float2int_rn(fmaf(vv[i], 32.0f, 64.0f));
                if ((unsigned)k_ < (unsigned)NL) sflag[d * NL + k_] = 1u;
            }
        }
        // scalar tail (nfloats % 4)
        for (int q = (n128 << 2) + gid; q < nfloats; q += gsz) {
            int d = (int)(q % 3);
            int k_ = __float2int_rn(fmaf(cflat[q], 32.0f, 64.0f));
            if ((unsigned)k_ < (unsigned)NL) sflag[d * NL + k_] = 1u;
        }
        __syncthreads();
        unsigned bal = __ballot_sync(~0u, sflag[wid * 32 + lane] != 0u);
        if (lane == 0 && bal) atomicOr(&g_maskbits[wid], bal);
        if (wid < 4) {
            int j = wid + 8;
            unsigned b2_ = __ballot_sync(~0u, sflag[j * 32 + lane] != 0u);
            if (lane == 0 && b2_) atomicOr(&g_maskbits[j], b2_);
        }
        __threadfence();
    }
#undef PROC_CHUNK
#undef PROC

    // ------------------------------------------------------------------
    // Fill out[NL .. nout) with c0 (vectorized, all blocks).
    // ------------------------------------------------------------------
    {
        const float c0 = s_c0;
        const float4 cv = make_float4(c0, c0, c0, c0);
        float4* out4 = (float4*)out;
        const int n4 = nout >> 2;
        for (int q = (NL / 4) + gid; q < n4; q += gsz) out4[q] = cv;
        for (int q = (n4 << 2) + gid; q < nout; q += gsz)
            if (q >= NL) out[q] = c0;
    }

    // ------------------------------------------------------------------
    // Last block finalizes rows [0, NL) and resets scratch for replay.
    // ------------------------------------------------------------------
    __threadfence();
    if (tid == 0) {
        unsigned t = atomicAdd(&g_done, 1u);
        s_last = (t == (unsigned)(gridDim.x - 1)) ? 1 : 0;
    }
    __syncthreads();
    if (s_last) {
        __threadfence();  // acquire: all blocks' g_maskbits / g_pre visible
        if (tid < NL) {
            const int r = tid;
            unsigned fx = (__ldcg(&g_maskbits[(r >> 5)])     >> (r & 31)) & 1u;
            unsigned fy = (__ldcg(&g_maskbits[4 + (r >> 5)]) >> (r & 31)) & 1u;
            unsigned fz = (__ldcg(&g_maskbits[8 + (r >> 5)]) >> (r & 31)) & 1u;
            unsigned combo = fx | (fy << 1) | (fz << 2);
            if (r < nout) out[r] = __ldcg(&g_pre[combo * NL + r]);
        }
        __syncthreads();
        if (tid < 12) g_maskbits[tid] = 0u;   // reset for next replay
        if (tid == 0) { g_p1done = 0u; g_done = 0u; }
    }
}

// ---------------------------------------------------------------------------
extern "C" void kernel_launch(void* const* d_in, const int* in_sizes, int n_in,
                              void* d_out, int out_size) {
    const float* coords = (const float*)d_in[0];
    const float* lines0 = (const float*)d_in[1];
    const float* lines1 = (const float*)d_in[2];
    const float* lines2 = (const float*)d_in[3];
    const float* w1     = (const float*)d_in[4];
    const float* b1     = (const float*)d_in[5];
    const float* w2     = (const float*)d_in[6];
    const float* b2     = (const float*)d_in[7];
    float* out = (float*)d_out;

    const int nfloats = in_sizes[0];
    const int n128 = nfloats >> 2;

    k_fused<<<GRID, TPB>>>((const float4*)coords, n128, coords, nfloats,
                           lines0, lines1, lines2, w1, b1, w2, b2,
                           out, out_size);
}

// round 6
// speedup vs baseline: 3.0833x; 1.4667x over previous
#include <cuda_runtime.h>

#define NL 128   // rows of lines tables
#define CL 32    // embedding width
#define HD 128   // hidden dim
#define NFLAG (3 * NL)
#define SAMPB 128          // sampler blocks (8 chunks each = 1024 chunks, 1.5 MB)
#define TPB  256
#define GRID 592

// Persistent device scratch (allocations forbidden). g_maskbits/g_done reset
// by the finalizing block each launch; g_pre7 fully rewritten => deterministic
// graph replays.
__device__ unsigned g_maskbits[12];   // packed flags: [axis*4 + word32]
__device__ float    g_pre7[NL];       // head output per row, combo=7 (all set)
__device__ unsigned g_done;           // sampler arrival counter

__global__ __launch_bounds__(TPB) void k_fused(
    const float4* __restrict__ c4, int n128,
    const float*  __restrict__ cflat, int nfloats,
    const float*  __restrict__ lines0, const float* __restrict__ lines1,
    const float*  __restrict__ lines2, const float* __restrict__ w1,
    const float*  __restrict__ b1, const float* __restrict__ w2,
    const float*  __restrict__ b2, float* __restrict__ out, int nout)
{
    __shared__ unsigned sflag[NFLAG];
    __shared__ float    s_red[8];
    __shared__ float    s_feats[CL];
    __shared__ float    s_c0;
    __shared__ int      s_last;

    const int tid  = threadIdx.x;
    const int lane = tid & 31;
    const int wid  = tid >> 5;
    const bool sampler = (blockIdx.x < SAMPB);

    if (sampler)
        for (int i = tid; i < NFLAG; i += TPB) sflag[i] = 0u;

    // ------------------------------------------------------------------
    // c0 = sum_j w2_j * relu(b1_j) + b2   (needed by every block for fill)
    // ------------------------------------------------------------------
    {
        float v = 0.f;
        if (tid < HD) v = fmaxf(__ldg(&b1[tid]), 0.f) * __ldg(&w2[tid]);
        #pragma unroll
        for (int o = 16; o; o >>= 1) v += __shfl_down_sync(~0u, v, o);
        if (tid < HD && lane == 0) s_red[wid] = v;
        __syncthreads();
        if (tid == 0) s_c0 = s_red[0] + s_red[1] + s_red[2] + s_red[3] + __ldg(&b2[0]);
        __syncthreads();
    }

    // Axis bases for the chunked scan: warp reads 96 consecutive float4s;
    // flat idx f = 4*(w*96+lane+32s)+i, axis(f) = (lane+2s+i)%3 = (p+j)%3,
    // p = lane%3, compile-time j. k = round((v+2)*32) ==
    // __float2int_rn(fmaf(v,32,64)) bit-exactly.
    const int p = lane % 3;
    int e1 = p + 1; if (e1 == 3) e1 = 0;
    int e2 = e1 + 1; if (e2 == 3) e2 = 0;
    const unsigned B0 = (unsigned)p  * NL;
    const unsigned B1 = (unsigned)e1 * NL;
    const unsigned B2 = (unsigned)e2 * NL;

#define PROC(v, BB) {                                                \
        float t_ = fmaf((v), 32.0f, 64.0f);                          \
        int k_ = __float2int_rn(t_);                                 \
        if ((unsigned)k_ < (unsigned)NL) sflag[(BB) + k_] = 1u; }

#define PROC_CHUNK(f0, f1, f2)                                       \
        PROC(f0.x, B0) PROC(f0.y, B1) PROC(f0.z, B2) PROC(f0.w, B0)  \
        PROC(f1.x, B2) PROC(f1.y, B0) PROC(f1.z, B1) PROC(f1.w, B2)  \
        PROC(f2.x, B1) PROC(f2.y, B2) PROC(f2.z, B0) PROC(f2.w, B1)

    const int nchunks = n128 / 96;

    if (sampler) {
        // ---- sample scan: warp wg scans chunk wg (wg in 0..1023) ----
        const int wg = blockIdx.x * 8 + wid;
        if (wg < nchunks) {
            const int ba = wg * 96 + lane;
            float4 a0 = c4[ba];
            float4 a1 = c4[ba + 32];
            float4 a2 = c4[ba + 64];
            PROC_CHUNK(a0, a1, a2)
        }
        __syncthreads();
        // ---- merge: ballot-pack 12 words, atomicOr to global ----
        {
            unsigned bal = __ballot_sync(~0u, sflag[wid * 32 + lane] != 0u);
            if (lane == 0 && bal) atomicOr(&g_maskbits[wid], bal);
            if (wid < 4) {
                int j = wid + 8;
                unsigned bl2 = __ballot_sync(~0u, sflag[j * 32 + lane] != 0u);
                if (lane == 0 && bl2) atomicOr(&g_maskbits[j], bl2);
            }
        }
        // ---- g_pre7 row r = blockIdx.x (combo 7: all lines present) ----
        {
            const int r = blockIdx.x;
            if (tid < CL) {
                float x = __ldg(&lines0[r * CL + tid]);
                float y = __ldg(&lines1[r * CL + tid]);
                float z = __ldg(&lines2[r * CL + tid]);
                float f1 = x + y + z;
                float f2 = (x * y + x * z + y * z) / 0.4f;
                float f3 = x * y * z / 0.16000000000000003f;
                s_feats[tid] = f1 + f2 + f3;
            }
            __syncthreads();
            float term = 0.f;
            if (tid < HD) {
                float acc = __ldg(&b1[tid]);
                const float4* w4 = (const float4*)(w1 + tid * CL);
                #pragma unroll
                for (int q = 0; q < CL / 4; q++) {
                    float4 wv = __ldg(&w4[q]);
                    acc = fmaf(wv.x, s_feats[q * 4 + 0], acc);
                    acc = fmaf(wv.y, s_feats[q * 4 + 1], acc);
                    acc = fmaf(wv.z, s_feats[q * 4 + 2], acc);
                    acc = fmaf(wv.w, s_feats[q * 4 + 3], acc);
                }
                term = fmaxf(acc, 0.f) * __ldg(&w2[tid]);
            }
            #pragma unroll
            for (int o = 16; o; o >>= 1) term += __shfl_down_sync(~0u, term, o);
            __syncthreads();
            if (tid < HD && lane == 0) s_red[wid] = term;
            __syncthreads();
            if (tid == 0)
                g_pre7[r] = s_red[0] + s_red[1] + s_red[2] + s_red[3] + __ldg(&b2[0]);
        }
    }

    // ------------------------------------------------------------------
    // Fill out[NL .. nout) with c0 (all blocks; flag-independent).
    // ------------------------------------------------------------------
    const int gid = blockIdx.x * TPB + tid;
    const int gsz = GRID * TPB;
    {
        const float c0 = s_c0;
        const float4 cv = make_float4(c0, c0, c0, c0);
        float4* out4 = (float4*)out;
        const int n4 = nout >> 2;
        for (int q = (NL / 4) + gid; q < n4; q += gsz) out4[q] = cv;
        for (int q = (n4 << 2) + gid; q < nout; q += gsz)
            if (q >= NL) out[q] = c0;
    }

    if (!sampler) return;   // non-samplers are done — no barrier, no spin

    // ------------------------------------------------------------------
    // Last-arriving sampler finalizes rows [0, NL) and resets scratch.
    // ------------------------------------------------------------------
    __threadfence();
    if (tid == 0) {
        unsigned t = atomicAdd(&g_done, 1u);
        s_last = (t == (unsigned)(SAMPB - 1)) ? 1 : 0;
    }
    __syncthreads();
    if (!s_last) return;

    __threadfence();   // acquire: all samplers' g_maskbits / g_pre7 visible
    int comp;
    if (tid == 0) {
        int c = 1;
        #pragma unroll
        for (int i = 0; i < 12; i++)
            c &= (__ldcg(&g_maskbits[i]) == 0xFFFFFFFFu);
        s_last = c + 1;   // reuse smem: 2 = complete, 1 = fallback
    }
    __syncthreads();
    comp = s_last - 1;

    if (comp) {
        // Fast path (always taken for this dataset): every flag observed set
        // => combo 7 for all rows; remaining input provably cannot change
        // the output (flags are monotone).
        if (tid < NL && tid < nout) out[tid] = __ldcg(&g_pre7[tid]);
    } else {
        // --------------------------------------------------------------
        // Fallback (correctness for arbitrary inputs; never hit here):
        // this block alone scans the unsampled remainder, merges, then
        // computes each row with its actual combo.
        // --------------------------------------------------------------
        for (int w = SAMPB * 8 + wid; w < nchunks; w += 8) {
            const int ba = w * 96 + lane;
            float4 a0 = c4[ba];
            float4 a1 = c4[ba + 32];
            float4 a2 = c4[ba + 64];
            PROC_CHUNK(a0, a1, a2)
        }
        for (int q = nchunks * 96 + tid; q < n128; q += TPB) {
            float4 f = c4[q];
            float vv[4] = {f.x, f.y, f.z, f.w};
            #pragma unroll
            for (int i = 0; i < 4; i++) {
                int d = (int)(((q << 2) + i) % 3);
                int k_ = __float2int_rn(fmaf(vv[i], 32.0f, 64.0f));
                if ((unsigned)k_ < (unsigned)NL) sflag[d * NL + k_] = 1u;
            }
        }
        for (int q = (n128 << 2) + tid; q < nfloats; q += TPB) {
            int d = (int)(q % 3);
            int k_ = __float2int_rn(fmaf(cflat[q], 32.0f, 64.0f));
            if ((unsigned)k_ < (unsigned)NL) sflag[d * NL + k_] = 1u;
        }
        __syncthreads();
        {
            unsigned bal = __ballot_sync(~0u, sflag[wid * 32 + lane] != 0u);
            if (lane == 0 && bal) atomicOr(&g_maskbits[wid], bal);
            if (wid < 4) {
                int j = wid + 8;
                unsigned bl2 = __ballot_sync(~0u, sflag[j * 32 + lane] != 0u);
                if (lane == 0 && bl2) atomicOr(&g_maskbits[j], bl2);
            }
        }
        __threadfence();
        __syncthreads();
        for (int r = 0; r < NL && r < nout; r++) {
            unsigned fx = (__ldcg(&g_maskbits[(r >> 5)])     >> (r & 31)) & 1u;
            unsigned fy = (__ldcg(&g_maskbits[4 + (r >> 5)]) >> (r & 31)) & 1u;
            unsigned fz = (__ldcg(&g_maskbits[8 + (r >> 5)]) >> (r & 31)) & 1u;
            if (tid < CL) {
                float x = __ldg(&lines0[r * CL + tid]) * (float)fx;
                float y = __ldg(&lines1[r * CL + tid]) * (float)fy;
                float z = __ldg(&lines2[r * CL + tid]) * (float)fz;
                float f1 = x + y + z;
                float f2 = (x * y + x * z + y * z) / 0.4f;
                float f3 = x * y * z / 0.16000000000000003f;
                s_feats[tid] = f1 + f2 + f3;
            }
            __syncthreads();
            float term = 0.f;
            if (tid < HD) {
                float acc = __ldg(&b1[tid]);
                const float4* w4 = (const float4*)(w1 + tid * CL);
                #pragma unroll
                for (int q = 0; q < CL / 4; q++) {
                    float4 wv = __ldg(&w4[q]);
                    acc = fmaf(wv.x, s_feats[q * 4 + 0], acc);
                    acc = fmaf(wv.y, s_feats[q * 4 + 1], acc);
                    acc = fmaf(wv.z, s_feats[q * 4 + 2], acc);
                    acc = fmaf(wv.w, s_feats[q * 4 + 3], acc);
                }
                term = fmaxf(acc, 0.f) * __ldg(&w2[tid]);
            }
            #pragma unroll
            for (int o = 16; o; o >>= 1) term += __shfl_down_sync(~0u, term, o);
            __syncthreads();
            if (tid < HD && lane == 0) s_red[wid] = term;
            __syncthreads();
            if (tid == 0)
                out[r] = s_red[0] + s_red[1] + s_red[2] + s_red[3] + __ldg(&b2[0]);
            __syncthreads();
        }
    }
#undef PROC_CHUNK
#undef PROC

    // Reset scratch for the next graph replay.
    __syncthreads();
    if (tid < 12) g_maskbits[tid] = 0u;
    if (tid == 0) g_done = 0u;
}

// ---------------------------------------------------------------------------
extern "C" void kernel_launch(void* const* d_in, const int* in_sizes, int n_in,
                              void* d_out, int out_size) {
    const float* coords = (const float*)d_in[0];
    const float* lines0 = (const float*)d_in[1];
    const float* lines1 = (const float*)d_in[2];
    const float* lines2 = (const float*)d_in[3];
    const float* w1     = (const float*)d_in[4];
    const float* b1     = (const float*)d_in[5];
    const float* w2     = (const float*)d_in[6];
    const float* b2     = (const float*)d_in[7];
    float* out = (float*)d_out;

    const int nfloats = in_sizes[0];
    const int n128 = nfloats >> 2;

    k_fused<<<GRID, TPB>>>((const float4*)coords, n128, coords, nfloats,
                           lines0, lines1, lines2, w1, b1, w2, b2,
                           out, out_size);
}

// round 7
// speedup vs baseline: 3.3134x; 1.0746x over previous
#include <cuda_runtime.h>

#define NL 128   // rows of lines tables
#define CL 32    // embedding width
#define HD 128   // hidden dim
#define NFLAG (3 * NL)
#define SAMPB 64           // sampler blocks; 8 warps x 2 chunks = 1024 chunks (1.5 MB)
#define SAMPLE_CH (SAMPB * 16)
#define TPB  256
#define GRID 592

// Persistent device scratch (allocations forbidden). Reset by the last
// sampler each launch => deterministic graph replays.
__device__ unsigned g_maskbits[12];   // packed flags: [axis*4 + word32]
__device__ unsigned g_done;           // sampler arrival counter

__global__ __launch_bounds__(TPB) void k_fused(
    const float4* __restrict__ c4, int n128,
    const float*  __restrict__ cflat, int nfloats,
    const float*  __restrict__ lines0, const float* __restrict__ lines1,
    const float*  __restrict__ lines2, const float* __restrict__ w1,
    const float*  __restrict__ b1, const float* __restrict__ w2,
    const float*  __restrict__ b2, float* __restrict__ out, int nout)
{
    __shared__ unsigned sflag[NFLAG];
    __shared__ float    s_red[8];
    __shared__ float    s_feats[2][CL];
    __shared__ float    s_c0;
    __shared__ int      s_last;
    __shared__ unsigned s_m12[12];

    const int tid  = threadIdx.x;
    const int lane = tid & 31;
    const int wid  = tid >> 5;
    const bool sampler = (blockIdx.x < SAMPB);
    const int nchunks = n128 / 96;

    // Axis mapping: warp reads 96 consecutive float4s per chunk; flat idx
    // f = 4*(c*96+lane+32s)+i, axis(f) = (lane+2s+i)%3 = (p+j)%3 with
    // p = lane%3 and compile-time j. k = round((v+2)*32) ==
    // __float2int_rn(fmaf(v,32,64)) bit-exactly (pow-2 scale commutes with
    // fp32 rounding; round-half-even in both).
    const int p = lane % 3;
    int e1 = p + 1; if (e1 == 3) e1 = 0;
    int e2 = e1 + 1; if (e2 == 3) e2 = 0;
    const unsigned B0 = (unsigned)p  * NL;
    const unsigned B1 = (unsigned)e1 * NL;
    const unsigned B2 = (unsigned)e2 * NL;

#define PROC(v, BB) {                                                \
        float t_ = fmaf((v), 32.0f, 64.0f);                          \
        int k_ = __float2int_rn(t_);                                 \
        if ((unsigned)k_ < (unsigned)NL) sflag[(BB) + k_] = 1u; }

#define PROC_CHUNK(f0, f1, f2)                                       \
        PROC(f0.x, B0) PROC(f0.y, B1) PROC(f0.z, B2) PROC(f0.w, B0)  \
        PROC(f1.x, B2) PROC(f1.y, B0) PROC(f1.z, B1) PROC(f1.w, B2)  \
        PROC(f2.x, B1) PROC(f2.y, B2) PROC(f2.z, B0) PROC(f2.w, B1)

    // ---- issue sample-scan loads FIRST (overlap with c0 latency) ----
    float4 a0, a1, a2, d0, d1, d2;
    bool va = false, vd = false;
    if (sampler) {
        for (int i = tid; i < NFLAG; i += TPB) sflag[i] = 0u;
        const int cA = (blockIdx.x * 8 + wid) * 2;
        const int cB = cA + 1;
        if (cA < nchunks) {
            va = true;
            const int ba = cA * 96 + lane;
            a0 = c4[ba]; a1 = c4[ba + 32]; a2 = c4[ba + 64];
        }
        if (cB < nchunks) {
            vd = true;
            const int bb = cB * 96 + lane;
            d0 = c4[bb]; d1 = c4[bb + 32]; d2 = c4[bb + 64];
        }
    }

    // ------------------------------------------------------------------
    // c0 = sum_j w2_j * relu(b1_j) + b2   (all blocks; needed for fill)
    // ------------------------------------------------------------------
    {
        float v = 0.f;
        if (tid < HD) v = fmaxf(__ldg(&b1[tid]), 0.f) * __ldg(&w2[tid]);
        #pragma unroll
        for (int o = 16; o; o >>= 1) v += __shfl_down_sync(~0u, v, o);
        if (tid < HD && lane == 0) s_red[wid] = v;
        __syncthreads();
        if (tid == 0) s_c0 = s_red[0] + s_red[1] + s_red[2] + s_red[3] + __ldg(&b2[0]);
        __syncthreads();
    }

    if (sampler) {
        // ---- consume sample loads into shared flags ----
        if (va) { PROC_CHUNK(a0, a1, a2) }
        if (vd) { PROC_CHUNK(d0, d1, d2) }
        __syncthreads();
        // ---- merge: ballot-pack 12 words, atomicOr to global ----
        {
            unsigned bal = __ballot_sync(~0u, sflag[wid * 32 + lane] != 0u);
            if (lane == 0 && bal) atomicOr(&g_maskbits[wid], bal);
            if (wid < 4) {
                int j = wid + 8;
                unsigned bl2 = __ballot_sync(~0u, sflag[j * 32 + lane] != 0u);
                if (lane == 0 && bl2) atomicOr(&g_maskbits[j], bl2);
            }
        }
        // ---- combo-7 rows r0, r1: compute and write out[] DIRECTLY ----
        // (optimistic: correct whenever masks saturate; fallback overwrites)
        {
            const int half = tid >> 7;           // 0 or 1 -> row select
            const int ht   = tid & 127;          // thread within half
            const int r    = blockIdx.x * 2 + half;
            if (ht < CL) {
                float x = __ldg(&lines0[r * CL + ht]);
                float y = __ldg(&lines1[r * CL + ht]);
                float z = __ldg(&lines2[r * CL + ht]);
                float f1 = x + y + z;
                float f2 = (x * y + x * z + y * z) / 0.4f;
                float f3 = x * y * z / 0.16000000000000003f;
                s_feats[half][ht] = f1 + f2 + f3;
            }
            __syncthreads();
            float acc = __ldg(&b1[ht]);
            const float4* w4 = (const float4*)(w1 + ht * CL);
            #pragma unroll
            for (int q = 0; q < CL / 4; q++) {
                float4 wv = __ldg(&w4[q]);
                acc = fmaf(wv.x, s_feats[half][q * 4 + 0], acc);
                acc = fmaf(wv.y, s_feats[half][q * 4 + 1], acc);
                acc = fmaf(wv.z, s_feats[half][q * 4 + 2], acc);
                acc = fmaf(wv.w, s_feats[half][q * 4 + 3], acc);
            }
            float term = fmaxf(acc, 0.f) * __ldg(&w2[ht]);
            #pragma unroll
            for (int o = 16; o; o >>= 1) term += __shfl_down_sync(~0u, term, o);
            if (lane == 0) s_red[wid] = term;
            __syncthreads();
            if (tid == 0 && r - half < nout) {  // r0 = 2*bid
                float v0 = s_red[0] + s_red[1] + s_red[2] + s_red[3] + __ldg(&b2[0]);
                out[blockIdx.x * 2] = v0;
            }
            if (tid == 128 && r < nout) {
                float v1 = s_red[4] + s_red[5] + s_red[6] + s_red[7] + __ldg(&b2[0]);
                out[r] = v1;
            }
        }
        // ---- arrival (BEFORE fill, so the check overlaps others' fill) ----
        __threadfence();
        if (tid == 0) {
            unsigned t = atomicAdd(&g_done, 1u);
            s_last = (t == (unsigned)(SAMPB - 1)) ? 1 : 0;
        }
        __syncthreads();
    }

    // ------------------------------------------------------------------
    // Fill out[NL .. nout) with c0 (all blocks; flag-independent).
    // ------------------------------------------------------------------
    const int gid = blockIdx.x * TPB + tid;
    const int gsz = GRID * TPB;
    {
        const float c0 = s_c0;
        const float4 cv = make_float4(c0, c0, c0, c0);
        float4* out4 = (float4*)out;
        const int n4 = nout >> 2;
        for (int q = (NL / 4) + gid; q < n4; q += gsz) out4[q] = cv;
        for (int q = (n4 << 2) + gid; q < nout; q += gsz)
            if (q >= NL) out[q] = c0;
    }

    if (!sampler || !s_last) return;

    // ------------------------------------------------------------------
    // Last-arriving sampler: verify saturation; fast path = nothing to do.
    // ------------------------------------------------------------------
    __threadfence();   // acquire: all samplers' g_maskbits / out[] visible
    if (tid == 0) {
        int c = 1;
        #pragma unroll
        for (int i = 0; i < 12; i++)
            c &= (__ldcg(&g_maskbits[i]) == 0xFFFFFFFFu);
        s_last = c + 1;   // 2 = complete, 1 = fallback
    }
    __syncthreads();

    if (s_last == 1) {
        // --------------------------------------------------------------
        // Fallback (correct for arbitrary inputs; not hit for this data):
        // scan the unsampled remainder, merge, recompute all 128 rows
        // with their actual combos (overwrites the optimistic values).
        // --------------------------------------------------------------
        for (int c = SAMPLE_CH + wid; c < nchunks; c += 8) {
            const int ba = c * 96 + lane;
            float4 f0 = c4[ba];
            float4 f1 = c4[ba + 32];
            float4 f2 = c4[ba + 64];
            PROC_CHUNK(f0, f1, f2)
        }
        for (int q = nchunks * 96 + tid; q < n128; q += TPB) {
            float4 f = c4[q];
            float vv[4] = {f.x, f.y, f.z, f.w};
            #pragma unroll
            for (int i = 0; i < 4; i++) {
                int d = (int)(((q << 2) + i) % 3);
                int k_ = __float2int_rn(fmaf(vv[i], 32.0f, 64.0f));
                if ((unsigned)k_ < (unsigned)NL) sflag[d * NL + k_] = 1u;
            }
        }
        for (int q = (n128 << 2) + tid; q < nfloats; q += TPB) {
            int d = (int)(q % 3);
            int k_ = __float2int_rn(fmaf(cflat[q], 32.0f, 64.0f));
            if ((unsigned)k_ < (unsigned)NL) sflag[d * NL + k_] = 1u;
        }
        __syncthreads();
        {
            unsigned bal = __ballot_sync(~0u, sflag[wid * 32 + lane] != 0u);
            if (lane == 0) s_m12[wid] = bal | __ldcg(&g_maskbits[wid]);
            if (wid < 4) {
                int j = wid + 8;
                unsigned bl2 = __ballot_sync(~0u, sflag[j * 32 + lane] != 0u);
                if (lane == 0) s_m12[j] = bl2 | __ldcg(&g_maskbits[j]);
            }
        }
        __syncthreads();
        for (int r = 0; r < NL && r < nout; r++) {
            unsigned fx = (s_m12[(r >> 5)]     >> (r & 31)) & 1u;
            unsigned fy = (s_m12[4 + (r >> 5)] >> (r & 31)) & 1u;
            unsigned fz = (s_m12[8 + (r >> 5)] >> (r & 31)) & 1u;
            if (tid < CL) {
                float x = __ldg(&lines0[r * CL + tid]) * (float)fx;
                float y = __ldg(&lines1[r * CL + tid]) * (float)fy;
                float z = __ldg(&lines2[r * CL + tid]) * (float)fz;
                float f1 = x + y + z;
                float f2 = (x * y + x * z + y * z) / 0.4f;
                float f3 = x * y * z / 0.16000000000000003f;
                s_feats[0][tid] = f1 + f2 + f3;
            }
            __syncthreads();
            float term = 0.f;
            if (tid < HD) {
                float acc = __ldg(&b1[tid]);
                const float4* w4 = (const float4*)(w1 + tid * CL);
                #pragma unroll
                for (int q = 0; q < CL / 4; q++) {
                    float4 wv = __ldg(&w4[q]);
                    acc = fmaf(wv.x, s_feats[0][q * 4 + 0], acc);
                    acc = fmaf(wv.y, s_feats[0][q * 4 + 1], acc);
                    acc = fmaf(wv.z, s_feats[0][q * 4 + 2], acc);
                    acc = fmaf(wv.w, s_feats[0][q * 4 + 3], acc);
                }
                term = fmaxf(acc, 0.f) * __ldg(&w2[tid]);
            }
            #pragma unroll
            for (int o = 16; o; o >>= 1) term += __shfl_down_sync(~0u, term, o);
            __syncthreads();
            if (tid < HD && lane == 0) s_red[wid] = term;
            __syncthreads();
            if (tid == 0)
                out[r] = s_red[0] + s_red[1] + s_red[2] + s_red[3] + __ldg(&b2[0]);
            __syncthreads();
        }
    }
#undef PROC_CHUNK
#undef PROC

    // Reset scratch for the next graph replay.
    __syncthreads();
    if (tid < 12) g_maskbits[tid] = 0u;
    if (tid == 0) g_done = 0u;
}

// ---------------------------------------------------------------------------
extern "C" void kernel_launch(void* const* d_in, const int* in_sizes, int n_in,
                              void* d_out, int out_size) {
    const float* coords = (const float*)d_in[0];
    const float* lines0 = (const float*)d_in[1];
    const float* lines1 = (const float*)d_in[2];
    const float* lines2 = (const float*)d_in[3];
    const float* w1     = (const float*)d_in[4];
    const float* b1     = (const float*)d_in[5];
    const float* w2     = (const float*)d_in[6];
    const float* b2     = (const float*)d_in[7];
    float* out = (float*)d_out;

    const int nfloats = in_sizes[0];
    const int n128 = nfloats >> 2;

    k_fused<<<GRID, TPB>>>((const float4*)coords, n128, coords, nfloats,
                           lines0, lines1, lines2, w1, b1, w2, b2,
                           out, out_size);
}

// round 8
// speedup vs baseline: 3.9643x; 1.1964x over previous
#include <cuda_runtime.h>

#define NL 128   // rows of lines tables
#define CL 32    // embedding width
#define HD 128   // hidden dim
#define NFLAG (3 * NL)
#define SAMPB 64           // sampler blocks; 8 warps x 1 chunk = 512 chunks (0.75 MB)
#define SAMPLE_CH (SAMPB * 8)
#define TPB  256
#define GRID 592

// Persistent device scratch (allocations forbidden). Reset by the last
// sampler each launch => deterministic graph replays.
__device__ unsigned g_maskbits[12];   // packed flags: [axis*4 + word32]
__device__ unsigned g_done;           // sampler arrival counter

__global__ __launch_bounds__(TPB) void k_fused(
    const float4* __restrict__ c4, int n128,
    const float*  __restrict__ cflat, int nfloats,
    const float*  __restrict__ lines0, const float* __restrict__ lines1,
    const float*  __restrict__ lines2, const float* __restrict__ w1,
    const float*  __restrict__ b1, const float* __restrict__ w2,
    const float*  __restrict__ b2, float* __restrict__ out, int nout)
{
    const int tid  = threadIdx.x;
    const int lane = tid & 31;
    const int wid  = tid >> 5;

    // ==================================================================
    // FILL TRACK (blocks SAMPB..GRID-1): c0 + fill out[NL..nout), exit.
    // No shared memory, no block syncs: one DRAM window + stores.
    // ==================================================================
    if (blockIdx.x >= SAMPB) {
        float v = 0.f;
        #pragma unroll
        for (int i = 0; i < 4; i++) {
            float bb = __ldg(&b1[lane + 32 * i]);
            float ww = __ldg(&w2[lane + 32 * i]);
            v = fmaf(fmaxf(bb, 0.f), ww, v);
        }
        #pragma unroll
        for (int o = 16; o; o >>= 1) v += __shfl_xor_sync(~0u, v, o);
        const float c0 = v + __ldg(&b2[0]);

        const int gid = (blockIdx.x - SAMPB) * TPB + tid;
        const int gsz = (GRID - SAMPB) * TPB;
        const float4 cv = make_float4(c0, c0, c0, c0);
        float4* out4 = (float4*)out;
        const int n4 = nout >> 2;
        for (int q = (NL / 4) + gid; q < n4; q += gsz) out4[q] = cv;
        for (int q = (n4 << 2) + gid; q < nout; q += gsz)
            if (q >= NL) out[q] = c0;
        return;
    }

    // ==================================================================
    // SAMPLER TRACK (blocks 0..SAMPB-1)
    // ==================================================================
    __shared__ unsigned sflag[NFLAG];
    __shared__ float    s_feats[2][CL];
    __shared__ float    s_red[8];
    __shared__ int      s_last;
    __shared__ unsigned s_m12[12];

    const int nchunks = n128 / 96;

    // Axis mapping: warp reads 96 consecutive float4s per chunk; flat idx
    // f = 4*(c*96+lane+32s)+i, axis(f) = (lane+2s+i)%3 = (p+j)%3 with
    // p = lane%3, compile-time j. k = round((v+2)*32) ==
    // __float2int_rn(fmaf(v,32,64)) bit-exactly (pow-2 scale commutes with
    // fp32 rounding; round-half-even in both).
    const int p = lane % 3;
    int e1 = p + 1; if (e1 == 3) e1 = 0;
    int e2 = e1 + 1; if (e2 == 3) e2 = 0;
    const unsigned B0 = (unsigned)p  * NL;
    const unsigned B1 = (unsigned)e1 * NL;
    const unsigned B2 = (unsigned)e2 * NL;

#define PROC(v, BB) {                                                \
        float t_ = fmaf((v), 32.0f, 64.0f);                          \
        int k_ = __float2int_rn(t_);                                 \
        if ((unsigned)k_ < (unsigned)NL) sflag[(BB) + k_] = 1u; }

#define PROC_CHUNK(f0, f1, f2)                                       \
        PROC(f0.x, B0) PROC(f0.y, B1) PROC(f0.z, B2) PROC(f0.w, B0)  \
        PROC(f1.x, B2) PROC(f1.y, B0) PROC(f1.z, B1) PROC(f1.w, B2)  \
        PROC(f2.x, B1) PROC(f2.y, B2) PROC(f2.z, B0) PROC(f2.w, B1)

    // ---- zero shared flags ----
    for (int i = tid; i < NFLAG; i += TPB) sflag[i] = 0u;

    // ---- issue ALL independent loads in one window ----
    const int ch = blockIdx.x * 8 + wid;
    const bool va = (ch < nchunks);
    float4 a0, a1, a2;
    if (va) {
        const int ba = ch * 96 + lane;
        a0 = c4[ba]; a1 = c4[ba + 32]; a2 = c4[ba + 64];
    }
    const int half = tid >> 7;          // 0/1: which output row this half owns
    const int ht   = tid & 127;
    const int r    = blockIdx.x * 2 + half;
    float lx = 0.f, ly = 0.f, lz = 0.f;
    if (ht < CL) {
        lx = __ldg(&lines0[r * CL + ht]);
        ly = __ldg(&lines1[r * CL + ht]);
        lz = __ldg(&lines2[r * CL + ht]);
    }
    float4 wreg[8];
    {
        const float4* w4 = (const float4*)(w1 + ht * CL);
        #pragma unroll
        for (int q = 0; q < 8; q++) wreg[q] = __ldg(&w4[q]);
    }
    const float b1v = __ldg(&b1[ht]);
    const float w2v = __ldg(&w2[ht]);
    const float b2v = __ldg(&b2[0]);

    // ---- feats (register math; own slot, no race) ----
    if (ht < CL) {
        float f1 = lx + ly + lz;
        float f2 = (lx * ly + lx * lz + ly * lz) / 0.4f;
        float f3 = lx * ly * lz / 0.16000000000000003f;
        s_feats[half][ht] = f1 + f2 + f3;
    }
    __syncthreads();   // sflag zeroing complete before PROC stores

    if (va) { PROC_CHUNK(a0, a1, a2) }
    __syncthreads();

    // ---- merge: ballot-pack 12 words, atomicOr to global ----
    {
        unsigned bal = __ballot_sync(~0u, sflag[wid * 32 + lane] != 0u);
        if (lane == 0 && bal) atomicOr(&g_maskbits[wid], bal);
        if (wid < 4) {
            int j = wid + 8;
            unsigned bl2 = __ballot_sync(~0u, sflag[j * 32 + lane] != 0u);
            if (lane == 0 && bl2) atomicOr(&g_maskbits[j], bl2);
        }
    }

    // ---- combo-7 MLP for rows 2*bid, 2*bid+1; optimistic direct write ----
    {
        float acc = b1v;
        #pragma unroll
        for (int q = 0; q < 8; q++) {
            acc = fmaf(wreg[q].x, s_feats[half][q * 4 + 0], acc);
            acc = fmaf(wreg[q].y, s_feats[half][q * 4 + 1], acc);
            acc = fmaf(wreg[q].z, s_feats[half][q * 4 + 2], acc);
            acc = fmaf(wreg[q].w, s_feats[half][q * 4 + 3], acc);
        }
        float term = fmaxf(acc, 0.f) * w2v;
        #pragma unroll
        for (int o = 16; o; o >>= 1) term += __shfl_down_sync(~0u, term, o);
        if (lane == 0) s_red[wid] = term;
        __syncthreads();
        if (tid == 0 && blockIdx.x * 2 < nout)
            out[blockIdx.x * 2] = s_red[0] + s_red[1] + s_red[2] + s_red[3] + b2v;
        if (tid == 128 && r < nout)
            out[r] = s_red[4] + s_red[5] + s_red[6] + s_red[7] + b2v;
    }

    // ---- arrival; last sampler finalizes ----
    __threadfence();
    if (tid == 0) {
        unsigned t = atomicAdd(&g_done, 1u);
        s_last = (t == (unsigned)(SAMPB - 1)) ? 1 : 0;
    }
    __syncthreads();
    if (!s_last) return;

    __threadfence();   // acquire: all samplers' g_maskbits / out[] visible
    if (tid == 0) {
        int c = 1;
        #pragma unroll
        for (int i = 0; i < 12; i++)
            c &= (__ldcg(&g_maskbits[i]) == 0xFFFFFFFFu);
        s_last = c + 1;   // 2 = saturated (fast path: nothing to do), 1 = fallback
    }
    __syncthreads();

    if (s_last == 1) {
        // --------------------------------------------------------------
        // Fallback (correct for arbitrary inputs; statistically never hit
        // for this data): scan the unsampled remainder, merge, recompute
        // all 128 rows with their actual combos (overwrites optimistic).
        // --------------------------------------------------------------
        for (int c = SAMPLE_CH + wid; c < nchunks; c += 8) {
            const int ba = c * 96 + lane;
            float4 f0 = c4[ba];
            float4 f1 = c4[ba + 32];
            float4 f2 = c4[ba + 64];
            PROC_CHUNK(f0, f1, f2)
        }
        for (int q = nchunks * 96 + tid; q < n128; q += TPB) {
            float4 f = c4[q];
            float vv[4] = {f.x, f.y, f.z, f.w};
            #pragma unroll
            for (int i = 0; i < 4; i++) {
                int d = (int)(((q << 2) + i) % 3);
                int k_ = __float2int_rn(fmaf(vv[i], 32.0f, 64.0f));
                if ((unsigned)k_ < (unsigned)NL) sflag[d * NL + k_] = 1u;
            }
        }
        for (int q = (n128 << 2) + tid; q < nfloats; q += TPB) {
            int d = (int)(q % 3);
            int k_ = __float2int_rn(fmaf(cflat[q], 32.0f, 64.0f));
            if ((unsigned)k_ < (unsigned)NL) sflag[d * NL + k_] = 1u;
        }
        __syncthreads();
        {
            unsigned bal = __ballot_sync(~0u, sflag[wid * 32 + lane] != 0u);
            if (lane == 0) s_m12[wid] = bal | __ldcg(&g_maskbits[wid]);
            if (wid < 4) {
                int j = wid + 8;
                unsigned bl2 = __ballot_sync(~0u, sflag[j * 32 + lane] != 0u);
                if (lane == 0) s_m12[j] = bl2 | __ldcg(&g_maskbits[j]);
            }
        }
        __syncthreads();
        for (int rr = 0; rr < NL && rr < nout; rr++) {
            unsigned fx = (s_m12[(rr >> 5)]     >> (rr & 31)) & 1u;
            unsigned fy = (s_m12[4 + (rr >> 5)] >> (rr & 31)) & 1u;
            unsigned fz = (s_m12[8 + (rr >> 5)] >> (rr & 31)) & 1u;
            if (tid < CL) {
                float x = __ldg(&lines0[rr * CL + tid]) * (float)fx;
                float y = __ldg(&lines1[rr * CL + tid]) * (float)fy;
                float z = __ldg(&lines2[rr * CL + tid]) * (float)fz;
                float f1 = x + y + z;
                float f2 = (x * y + x * z + y * z) / 0.4f;
                float f3 = x * y * z / 0.16000000000000003f;
                s_feats[0][tid] = f1 + f2 + f3;
            }
            __syncthreads();
            float term = 0.f;
            if (tid < HD) {
                float acc = __ldg(&b1[tid]);
                const float4* w4 = (const float4*)(w1 + tid * CL);
                #pragma unroll
                for (int q = 0; q < CL / 4; q++) {
                    float4 wv = __ldg(&w4[q]);
                    acc = fmaf(wv.x, s_feats[0][q * 4 + 0], acc);
                    acc = fmaf(wv.y, s_feats[0][q * 4 + 1], acc);
                    acc = fmaf(wv.z, s_feats[0][q * 4 + 2], acc);
                    acc = fmaf(wv.w, s_feats[0][q * 4 + 3], acc);
                }
                term = fmaxf(acc, 0.f) * __ldg(&w2[tid]);
            }
            #pragma unroll
            for (int o = 16; o; o >>= 1) term += __shfl_down_sync(~0u, term, o);
            __syncthreads();
            if (tid < HD && lane == 0) s_red[wid] = term;
            __syncthreads();
            if (tid == 0)
                out[rr] = s_red[0] + s_red[1] + s_red[2] + s_red[3] + __ldg(&b2[0]);
            __syncthreads();
        }
    }
#undef PROC_CHUNK
#undef PROC

    // Reset scratch for the next graph replay.
    __syncthreads();
    if (tid < 12) g_maskbits[tid] = 0u;
    if (tid == 0) g_done = 0u;
}

// ---------------------------------------------------------------------------
extern "C" void kernel_launch(void* const* d_in, const int* in_sizes, int n_in,
                              void* d_out, int out_size) {
    const float* coords = (const float*)d_in[0];
    const float* lines0 = (const float*)d_in[1];
    const float* lines1 = (const float*)d_in[2];
    const float* lines2 = (const float*)d_in[3];
    const float* w1     = (const float*)d_in[4];
    const float* b1     = (const float*)d_in[5];
    const float* w2     = (const float*)d_in[6];
    const float* b2     = (const float*)d_in[7];
    float* out = (float*)d_out;

    const int nfloats = in_sizes[0];
    const int n128 = nfloats >> 2;

    k_fused<<<GRID, TPB>>>((const float4*)coords, n128, coords, nfloats,
                           lines0, lines1, lines2, w1, b1, w2, b2,
                           out, out_size);
}

// round 9
// speedup vs baseline: 4.0959x; 1.0332x over previous
#include <cuda_runtime.h>

#define NL 128   // rows of lines tables
#define CL 32    // embedding width
#define HD 128   // hidden dim
#define NFLAG (3 * NL)
#define SAMPB 16                    // sampler blocks
#define SAMPLE_CH (SAMPB * 8 * 2)   // 8 warps x 2 chunks each = 256 chunks
#define ROWB  64                    // row blocks (2 rows each)
#define TPB  256
#define GRID 592

// Persistent device scratch (allocations forbidden). Net change per launch is
// zero for counters; maskbits reset by the checker => deterministic replays.
__device__ unsigned g_maskbits[12];   // packed flags: [axis*4 + word32]
__device__ unsigned g_scnt;           // sampler arrival counter
__device__ unsigned g_rcnt;           // row-block arrival counter (fallback gate)

__global__ __launch_bounds__(TPB) void k_fused(
    const float4* __restrict__ c4, int n128,
    const float*  __restrict__ cflat, int nfloats,
    const float*  __restrict__ lines0, const float* __restrict__ lines1,
    const float*  __restrict__ lines2, const float* __restrict__ w1,
    const float*  __restrict__ b1, const float* __restrict__ w2,
    const float*  __restrict__ b2, float* __restrict__ out, int nout)
{
    const int tid  = threadIdx.x;
    const int lane = tid & 31;
    const int wid  = tid >> 5;

    // ==================================================================
    // FILL TRACK (blocks >= SAMPB+ROWB): c0 + fill out[NL..nout), exit.
    // ==================================================================
    if (blockIdx.x >= SAMPB + ROWB) {
        float v = 0.f;
        #pragma unroll
        for (int i = 0; i < 4; i++) {
            float bb = __ldg(&b1[lane + 32 * i]);
            float ww = __ldg(&w2[lane + 32 * i]);
            v = fmaf(fmaxf(bb, 0.f), ww, v);
        }
        #pragma unroll
        for (int o = 16; o; o >>= 1) v += __shfl_xor_sync(~0u, v, o);
        const float c0 = v + __ldg(&b2[0]);

        const int gid = (blockIdx.x - SAMPB - ROWB) * TPB + tid;
        const int gsz = (GRID - SAMPB - ROWB) * TPB;
        const float4 cv = make_float4(c0, c0, c0, c0);
        float4* out4 = (float4*)out;
        const int n4 = nout >> 2;
        for (int q = (NL / 4) + gid; q < n4; q += gsz) out4[q] = cv;
        for (int q = (n4 << 2) + gid; q < nout; q += gsz)
            if (q >= NL) out[q] = c0;
        return;
    }

    // ==================================================================
    // ROW TRACK (blocks SAMPB..SAMPB+ROWB-1): 2 combo-7 rows, optimistic
    // direct write; fire-and-forget RED arrival (fallback ordering gate).
    // ==================================================================
    if (blockIdx.x >= SAMPB) {
        __shared__ float s_feats[2][CL];
        __shared__ float s_red[8];
        const int rb   = blockIdx.x - SAMPB;
        const int half = tid >> 7;
        const int ht   = tid & 127;
        const int r    = rb * 2 + half;

        float lx = 0.f, ly = 0.f, lz = 0.f;
        if (ht < CL) {
            lx = __ldg(&lines0[r * CL + ht]);
            ly = __ldg(&lines1[r * CL + ht]);
            lz = __ldg(&lines2[r * CL + ht]);
        }
        float4 wreg[8];
        {
            const float4* w4 = (const float4*)(w1 + ht * CL);
            #pragma unroll
            for (int q = 0; q < 8; q++) wreg[q] = __ldg(&w4[q]);
        }
        const float b1v = __ldg(&b1[ht]);
        const float w2v = __ldg(&w2[ht]);
        const float b2v = __ldg(&b2[0]);

        if (ht < CL) {
            float f1 = lx + ly + lz;
            float f2 = (lx * ly + lx * lz + ly * lz) / 0.4f;
            float f3 = lx * ly * lz / 0.16000000000000003f;
            s_feats[half][ht] = f1 + f2 + f3;
        }
        __syncthreads();

        float acc = b1v;
        #pragma unroll
        for (int q = 0; q < 8; q++) {
            acc = fmaf(wreg[q].x, s_feats[half][q * 4 + 0], acc);
            acc = fmaf(wreg[q].y, s_feats[half][q * 4 + 1], acc);
            acc = fmaf(wreg[q].z, s_feats[half][q * 4 + 2], acc);
            acc = fmaf(wreg[q].w, s_feats[half][q * 4 + 3], acc);
        }
        float term = fmaxf(acc, 0.f) * w2v;
        #pragma unroll
        for (int o = 16; o; o >>= 1) term += __shfl_down_sync(~0u, term, o);
        if (lane == 0) s_red[wid] = term;
        __syncthreads();
        if (tid == 0 && rb * 2 < nout)
            out[rb * 2] = s_red[0] + s_red[1] + s_red[2] + s_red[3] + b2v;
        if (tid == 128 && r < nout)
            out[r] = s_red[4] + s_red[5] + s_red[6] + s_red[7] + b2v;

        __threadfence();
        if (tid == 0) atomicAdd(&g_rcnt, 1u);   // return unused -> RED
        return;
    }

    // ==================================================================
    // SAMPLER TRACK (blocks 0..SAMPB-1): 2 chunks/warp -> flags -> merge.
    // ==================================================================
    __shared__ unsigned sflag[NFLAG];
    __shared__ float    s_feats1[CL];
    __shared__ float    s_red1[8];
    __shared__ int      s_last;
    __shared__ unsigned s_m12[12];

    const int nchunks = n128 / 96;

    // Axis mapping: warp reads 96 consecutive float4s per chunk; flat idx
    // f = 4*(c*96+lane+32s)+i, axis(f) = (lane+2s+i)%3 = (p+j)%3 with
    // p = lane%3, compile-time j. k = round((v+2)*32) ==
    // __float2int_rn(fmaf(v,32,64)) bit-exactly.
    const int p = lane % 3;
    int e1 = p + 1; if (e1 == 3) e1 = 0;
    int e2 = e1 + 1; if (e2 == 3) e2 = 0;
    const unsigned B0 = (unsigned)p  * NL;
    const unsigned B1 = (unsigned)e1 * NL;
    const unsigned B2 = (unsigned)e2 * NL;

#define PROC(v, BB) {                                                \
        float t_ = fmaf((v), 32.0f, 64.0f);                          \
        int k_ = __float2int_rn(t_);                                 \
        if ((unsigned)k_ < (unsigned)NL) sflag[(BB) + k_] = 1u; }

#define PROC_CHUNK(f0, f1, f2)                                       \
        PROC(f0.x, B0) PROC(f0.y, B1) PROC(f0.z, B2) PROC(f0.w, B0)  \
        PROC(f1.x, B2) PROC(f1.y, B0) PROC(f1.z, B1) PROC(f1.w, B2)  \
        PROC(f2.x, B1) PROC(f2.y, B2) PROC(f2.z, B0) PROC(f2.w, B1)

    for (int i = tid; i < NFLAG; i += TPB) sflag[i] = 0u;

    // Issue both chunks' loads in one window.
    const int cA = (blockIdx.x * 8 + wid) * 2;
    const int cB = cA + 1;
    const bool va = (cA < nchunks), vb = (cB < nchunks);
    float4 a0, a1, a2, d0, d1, d2;
    if (va) { const int ba = cA * 96 + lane; a0 = c4[ba]; a1 = c4[ba + 32]; a2 = c4[ba + 64]; }
    if (vb) { const int bb = cB * 96 + lane; d0 = c4[bb]; d1 = c4[bb + 32]; d2 = c4[bb + 64]; }
    __syncthreads();   // zeroing complete
    if (va) { PROC_CHUNK(a0, a1, a2) }
    if (vb) { PROC_CHUNK(d0, d1, d2) }
    __syncthreads();

    // Merge: ballot-pack 12 words, atomicOr to global.
    {
        unsigned bal = __ballot_sync(~0u, sflag[wid * 32 + lane] != 0u);
        if (lane == 0 && bal) atomicOr(&g_maskbits[wid], bal);
        if (wid < 4) {
            int j = wid + 8;
            unsigned bl2 = __ballot_sync(~0u, sflag[j * 32 + lane] != 0u);
            if (lane == 0 && bl2) atomicOr(&g_maskbits[j], bl2);
        }
    }
    __threadfence();
    if (tid == 0) {
        unsigned t = atomicAdd(&g_scnt, 1u);
        s_last = (t == (unsigned)(SAMPB - 1)) ? 1 : 0;
    }
    __syncthreads();
    if (!s_last) return;

    // ---- checker (last sampler) ----
    __threadfence();
    if (tid == 0) {
        int c = 1;
        #pragma unroll
        for (int i = 0; i < 12; i++)
            c &= (__ldcg(&g_maskbits[i]) == 0xFFFFFFFFu);
        s_last = c + 1;   // 2 = saturated, 1 = fallback
    }
    __syncthreads();

    if (s_last == 2) {
        // Fast path: rows already correct (combo 7 everywhere). Reset state.
        if (tid < 12) g_maskbits[tid] = 0u;      // safe: all sampler ORs done
        if (tid == 0) {
            atomicAdd(&g_scnt, (unsigned)-SAMPB);  // net 0 per launch
            atomicAdd(&g_rcnt, (unsigned)-ROWB);
        }
        return;
    }

    // ------------------------------------------------------------------
    // Fallback (correct for arbitrary inputs; statistically never hit):
    // wait for all optimistic row writes, rescan the unsampled remainder,
    // recompute all rows with true combos, reset state.
    // ------------------------------------------------------------------
    if (tid == 0) {
        unsigned c;
        do {
            asm volatile("ld.global.cg.u32 %0, [%1];" : "=r"(c) : "l"(&g_rcnt));
            if (c >= (unsigned)ROWB) break;
            __nanosleep(128);
        } while (true);
    }
    __syncthreads();

    for (int c = SAMPLE_CH + wid; c < nchunks; c += 8) {
        const int ba = c * 96 + lane;
        float4 f0 = c4[ba];
        float4 f1 = c4[ba + 32];
        float4 f2 = c4[ba + 64];
        PROC_CHUNK(f0, f1, f2)
    }
    for (int q = nchunks * 96 + tid; q < n128; q += TPB) {
        float4 f = c4[q];
        float vv[4] = {f.x, f.y, f.z, f.w};
        #pragma unroll
        for (int i = 0; i < 4; i++) {
            int d = (int)(((q << 2) + i) % 3);
            int k_ = __float2int_rn(fmaf(vv[i], 32.0f, 64.0f));
            if ((unsigned)k_ < (unsigned)NL) sflag[d * NL + k_] = 1u;
        }
    }
    for (int q = (n128 << 2) + tid; q < nfloats; q += TPB) {
        int d = (int)(q % 3);
        int k_ = __float2int_rn(fmaf(cflat[q], 32.0f, 64.0f));
        if ((unsigned)k_ < (unsigned)NL) sflag[d * NL + k_] = 1u;
    }
    __syncthreads();
    {
        unsigned bal = __ballot_sync(~0u, sflag[wid * 32 + lane] != 0u);
        if (lane == 0) s_m12[wid] = bal | __ldcg(&g_maskbits[wid]);
        if (wid < 4) {
            int j = wid + 8;
            unsigned bl2 = __ballot_sync(~0u, sflag[j * 32 + lane] != 0u);
            if (lane == 0) s_m12[j] = bl2 | __ldcg(&g_maskbits[j]);
        }
    }
    __syncthreads();
    for (int rr = 0; rr < NL && rr < nout; rr++) {
        unsigned fx = (s_m12[(rr >> 5)]     >> (rr & 31)) & 1u;
        unsigned fy = (s_m12[4 + (rr >> 5)] >> (rr & 31)) & 1u;
        unsigned fz = (s_m12[8 + (rr >> 5)] >> (rr & 31)) & 1u;
        if (tid < CL) {
            float x = __ldg(&lines0[rr * CL + tid]) * (float)fx;
            float y = __ldg(&lines1[rr * CL + tid]) * (float)fy;
            float z = __ldg(&lines2[rr * CL + tid]) * (float)fz;
            float f1 = x + y + z;
            float f2 = (x * y + x * z + y * z) / 0.4f;
            float f3 = x * y * z / 0.16000000000000003f;
            s_feats1[tid] = f1 + f2 + f3;
        }
        __syncthreads();
        float term = 0.f;
        if (tid < HD) {
            float acc = __ldg(&b1[tid]);
            const float4* w4 = (const float4*)(w1 + tid * CL);
            #pragma unroll
            for (int q = 0; q < CL / 4; q++) {
                float4 wv = __ldg(&w4[q]);
                acc = fmaf(wv.x, s_feats1[q * 4 + 0], acc);
                acc = fmaf(wv.y, s_feats1[q * 4 + 1], acc);
                acc = fmaf(wv.z, s_feats1[q * 4 + 2], acc);
                acc = fmaf(wv.w, s_feats1[q * 4 + 3], acc);
            }
            term = fmaxf(acc, 0.f) * __ldg(&w2[tid]);
        }
        #pragma unroll
        for (int o = 16; o; o >>= 1) term += __shfl_down_sync(~0u, term, o);
        __syncthreads();
        if (tid < HD && lane == 0) s_red1[wid] = term;
        __syncthreads();
        if (tid == 0)
            out[rr] = s_red1[0] + s_red1[1] + s_red1[2] + s_red1[3] + __ldg(&b2[0]);
        __syncthreads();
    }
#undef PROC_CHUNK
#undef PROC

    // Reset for next replay.
    __syncthreads();
    if (tid < 12) g_maskbits[tid] = 0u;
    if (tid == 0) { atomicExch(&g_rcnt, 0u); atomicExch(&g_scnt, 0u); }
}

// ---------------------------------------------------------------------------
extern "C" void kernel_launch(void* const* d_in, const int* in_sizes, int n_in,
                              void* d_out, int out_size) {
    const float* coords = (const float*)d_in[0];
    const float* lines0 = (const float*)d_in[1];
    const float* lines1 = (const float*)d_in[2];
    const float* lines2 = (const float*)d_in[3];
    const float* w1     = (const float*)d_in[4];
    const float* b1     = (const float*)d_in[5];
    const float* w2     = (const float*)d_in[6];
    const float* b2     = (const float*)d_in[7];
    float* out = (float*)d_out;

    const int nfloats = in_sizes[0];
    const int n128 = nfloats >> 2;

    k_fused<<<GRID, TPB>>>((const float4*)coords, n128, coords, nfloats,
                           lines0, lines1, lines2, w1, b1, w2, b2,
                           out, out_size);
}